// round 2
// baseline (speedup 1.0000x reference)
#include <cuda_runtime.h>
#include <cuda_fp16.h>
#include <cstdint>
#include <cstddef>

#define BATCH 1024
#define INF   512
#define OUTF  100000
#define OUTP  100096   // padded to multiple of 128

#define MARGIN_COS 0.8775825618903728f
#define MARGIN_SIN 0.4794255386042030f
#define LOGIT_SCALE 20.0f
#define W_PRESCALE 64.0f

// Scratch (device globals: allocation-free rule)
static __device__ __half d_fhat[BATCH * INF];                 // normalized features, fp16
static __device__ __half d_wh[(size_t)OUTP * INF];            // W * 64, fp16 (pad rows stay zero)
static __device__ float  d_winv[OUTP];                        // 1/(64*||w_c||)

// ---------------------------------------------------------------------------
// Kernel 1: normalize features rows (exact fp32 norm), write fp16
// ---------------------------------------------------------------------------
__global__ void norm_features_k(const float* __restrict__ f) {
    int b = blockIdx.x;
    int t = threadIdx.x;  // 128 threads, each handles one float4
    const float4* f4 = reinterpret_cast<const float4*>(f + (size_t)b * INF);
    float4 v = f4[t];
    float ss = v.x * v.x + v.y * v.y + v.z * v.z + v.w * v.w;
#pragma unroll
    for (int o = 16; o; o >>= 1) ss += __shfl_xor_sync(0xFFFFFFFFu, ss, o);
    __shared__ float red[4];
    if ((t & 31) == 0) red[t >> 5] = ss;
    __syncthreads();
    ss = red[0] + red[1] + red[2] + red[3];
    float inv = 1.0f / fmaxf(sqrtf(ss), 1e-12f);
    __half2* o2 = reinterpret_cast<__half2*>(d_fhat + (size_t)b * INF + t * 4);
    o2[0] = __floats2half2_rn(v.x * inv, v.y * inv);
    o2[1] = __floats2half2_rn(v.z * inv, v.w * inv);
}

// ---------------------------------------------------------------------------
// Kernel 2: convert weights fp32 -> fp16 (prescaled), exact inverse norms
// ---------------------------------------------------------------------------
__global__ void prep_weights_k(const float* __restrict__ w) {
    int c = blockIdx.x;
    int t = threadIdx.x;  // 128 threads
    __half2* o2 = reinterpret_cast<__half2*>(d_wh + (size_t)c * INF + t * 4);
    if (c < OUTF) {
        const float4* w4 = reinterpret_cast<const float4*>(w + (size_t)c * INF);
        float4 v = w4[t];
        float ss = v.x * v.x + v.y * v.y + v.z * v.z + v.w * v.w;
#pragma unroll
        for (int o = 16; o; o >>= 1) ss += __shfl_xor_sync(0xFFFFFFFFu, ss, o);
        __shared__ float red[4];
        if ((t & 31) == 0) red[t >> 5] = ss;
        __syncthreads();
        ss = red[0] + red[1] + red[2] + red[3];
        if (t == 0) d_winv[c] = 1.0f / (W_PRESCALE * fmaxf(sqrtf(ss), 1e-12f));
        o2[0] = __floats2half2_rn(v.x * W_PRESCALE, v.y * W_PRESCALE);
        o2[1] = __floats2half2_rn(v.z * W_PRESCALE, v.w * W_PRESCALE);
    } else {
        // pad rows: zero
        o2[0] = __floats2half2_rn(0.f, 0.f);
        o2[1] = __floats2half2_rn(0.f, 0.f);
        if (t == 0) d_winv[c] = 0.0f;
    }
}

// ---------------------------------------------------------------------------
// GEMM: 128x128x32 tiles, mma.sync.m16n8k16 fp16 -> fp32, fused ArcFace epilogue
// ---------------------------------------------------------------------------
__device__ __forceinline__ void ldsm4(uint32_t& r0, uint32_t& r1, uint32_t& r2, uint32_t& r3,
                                      const __half* p) {
    uint32_t a = (uint32_t)__cvta_generic_to_shared(p);
    asm volatile("ldmatrix.sync.aligned.m8n8.x4.shared.b16 {%0,%1,%2,%3},[%4];"
                 : "=r"(r0), "=r"(r1), "=r"(r2), "=r"(r3) : "r"(a));
}

__device__ __forceinline__ void mma16816(float* c, const uint32_t* a, uint32_t b0, uint32_t b1) {
    asm volatile(
        "mma.sync.aligned.m16n8k16.row.col.f32.f16.f16.f32 "
        "{%0,%1,%2,%3},{%4,%5,%6,%7},{%8,%9},{%0,%1,%2,%3};"
        : "+f"(c[0]), "+f"(c[1]), "+f"(c[2]), "+f"(c[3])
        : "r"(a[0]), "r"(a[1]), "r"(a[2]), "r"(a[3]), "r"(b0), "r"(b1));
}

#define BM 128
#define BN 128
#define BK 32
#define LDS 40  // padded row length in halves (conflict-free ldmatrix)

__global__ __launch_bounds__(256, 2)
void arcface_gemm_k(const int* __restrict__ targets, float* __restrict__ out) {
    const int tid  = threadIdx.x;
    const int lane = tid & 31;
    const int wid  = tid >> 5;
    const int wm   = wid & 1;   // 2 warps in M
    const int wn   = wid >> 1;  // 4 warps in N
    const int mblk = blockIdx.x * BM;
    const int nblk = blockIdx.y * BN;

    __shared__ __half As[2][BM * LDS];
    __shared__ __half Bs[2][BM * LDS];

    float acc[4][4][4];
#pragma unroll
    for (int i = 0; i < 4; i++)
#pragma unroll
        for (int j = 0; j < 4; j++)
#pragma unroll
            for (int k = 0; k < 4; k++) acc[i][j][k] = 0.0f;

    // global-load mapping: 2 uint4 per thread per tile (rows r and r+64)
    const int r  = tid >> 2;
    const int cg = (tid & 3) * 8;  // column offset in halves
    const __half* Ag = d_fhat + (size_t)(mblk + r) * INF + cg;
    const __half* Bg = d_wh   + (size_t)(nblk + r) * INF + cg;

    uint4 a0 = *reinterpret_cast<const uint4*>(Ag);
    uint4 a1 = *reinterpret_cast<const uint4*>(Ag + (size_t)64 * INF);
    uint4 b0 = *reinterpret_cast<const uint4*>(Bg);
    uint4 b1 = *reinterpret_cast<const uint4*>(Bg + (size_t)64 * INF);
    *reinterpret_cast<uint4*>(&As[0][r * LDS + cg])        = a0;
    *reinterpret_cast<uint4*>(&As[0][(r + 64) * LDS + cg]) = a1;
    *reinterpret_cast<uint4*>(&Bs[0][r * LDS + cg])        = b0;
    *reinterpret_cast<uint4*>(&Bs[0][(r + 64) * LDS + cg]) = b1;

    const int NKT = INF / BK;  // 16
#pragma unroll 2
    for (int kt = 0; kt < NKT; ++kt) {
        __syncthreads();
        const int cur = kt & 1;

        if (kt < NKT - 1) {
            const __half* Agn = Ag + (kt + 1) * BK;
            const __half* Bgn = Bg + (kt + 1) * BK;
            a0 = *reinterpret_cast<const uint4*>(Agn);
            a1 = *reinterpret_cast<const uint4*>(Agn + (size_t)64 * INF);
            b0 = *reinterpret_cast<const uint4*>(Bgn);
            b1 = *reinterpret_cast<const uint4*>(Bgn + (size_t)64 * INF);
        }

#pragma unroll
        for (int ks = 0; ks < 2; ++ks) {
            const int ko = ks * 16 + ((lane >> 4) << 3);
            uint32_t af[4][4];
#pragma unroll
            for (int mi = 0; mi < 4; ++mi) {
                int row = wm * 64 + mi * 16 + (lane & 15);
                ldsm4(af[mi][0], af[mi][1], af[mi][2], af[mi][3],
                      &As[cur][row * LDS + ko]);
            }
            uint32_t bf[2][4];
#pragma unroll
            for (int pi = 0; pi < 2; ++pi) {
                int row = wn * 32 + pi * 16 + (lane & 7) + (((lane >> 3) & 1) << 3);
                ldsm4(bf[pi][0], bf[pi][1], bf[pi][2], bf[pi][3],
                      &Bs[cur][row * LDS + ko]);
            }
            // bf[pi]: r0 = b_lo(n0-7), r1 = b_lo(n8-15), r2 = b_hi(n0-7), r3 = b_hi(n8-15)
#pragma unroll
            for (int mi = 0; mi < 4; ++mi)
#pragma unroll
                for (int ni = 0; ni < 4; ++ni) {
                    int pi = ni >> 1, sub = ni & 1;
                    mma16816(acc[mi][ni], af[mi], bf[pi][sub], bf[pi][sub + 2]);
                }
        }

        if (kt < NKT - 1) {
            const int nxt = cur ^ 1;
            *reinterpret_cast<uint4*>(&As[nxt][r * LDS + cg])        = a0;
            *reinterpret_cast<uint4*>(&As[nxt][(r + 64) * LDS + cg]) = a1;
            *reinterpret_cast<uint4*>(&Bs[nxt][r * LDS + cg])        = b0;
            *reinterpret_cast<uint4*>(&Bs[nxt][(r + 64) * LDS + cg]) = b1;
        }
    }

    // ---------------- epilogue ----------------
    const int rbase = mblk + wm * 64 + (lane >> 2);
    int tg[8];
#pragma unroll
    for (int mi = 0; mi < 4; ++mi) {
        tg[mi * 2 + 0] = targets[rbase + mi * 16];
        tg[mi * 2 + 1] = targets[rbase + mi * 16 + 8];
    }

#pragma unroll
    for (int ni = 0; ni < 4; ++ni) {
        const int c0 = nblk + wn * 32 + ni * 8 + (lane & 3) * 2;
        if (c0 >= OUTF) continue;
        const float2 wv = *reinterpret_cast<const float2*>(d_winv + c0);
#pragma unroll
        for (int mi = 0; mi < 4; ++mi) {
#pragma unroll
            for (int rr = 0; rr < 2; ++rr) {
                const int row = rbase + mi * 16 + rr * 8;
                float x0 = acc[mi][ni][rr * 2 + 0] * wv.x;
                float x1 = acc[mi][ni][rr * 2 + 1] * wv.y;
                x0 = fminf(fmaxf(x0, -1.0f), 1.0f);
                x1 = fminf(fmaxf(x1, -1.0f), 1.0f);
                const int t = tg[mi * 2 + rr];
                if (t == c0)
                    x0 = x0 * MARGIN_COS - sqrtf(fmaxf(1.0f - x0 * x0, 0.0f)) * MARGIN_SIN;
                if (t == c0 + 1)
                    x1 = x1 * MARGIN_COS - sqrtf(fmaxf(1.0f - x1 * x1, 0.0f)) * MARGIN_SIN;
                float2 o = make_float2(x0 * LOGIT_SCALE, x1 * LOGIT_SCALE);
                *reinterpret_cast<float2*>(out + (size_t)row * OUTF + c0) = o;
            }
        }
    }
}

// ---------------------------------------------------------------------------
extern "C" void kernel_launch(void* const* d_in, const int* in_sizes, int n_in,
                              void* d_out, int out_size) {
    const float* feat = (const float*)d_in[0];
    const int*   tgt  = (const int*)d_in[1];    // int32: JAX x64-disabled downcasts int64
    const float* w    = (const float*)d_in[2];
    float* out = (float*)d_out;

    norm_features_k<<<BATCH, 128>>>(feat);
    prep_weights_k<<<OUTP, 128>>>(w);
    dim3 grid(BATCH / BM, OUTP / BN);  // (8, 782); x = M innermost for L2 reuse of W tiles
    arcface_gemm_k<<<grid, 256>>>(tgt, out);
}